// round 7
// baseline (speedup 1.0000x reference)
#include <cuda_runtime.h>
#include <cuda_bf16.h>
#include <cstdint>

// Problem constants
#define BB   2
#define NB   32
#define PP   128
#define FF   32
#define HH   32
#define NODE_OUT 8
#define OUTD 32
#define BINS (BB*NB)            // 64
#define ROWS (BINS*PP)          // 8192
#define TI   8                  // i-rows per pair block

// Scratch (no cudaMalloc allowed)
__device__ float g_pa_buf[ROWS*OUTD];
__device__ float g_pb_buf[ROWS*OUTD];

// ---------- helpers ----------
__device__ __forceinline__ float eluf(float x) {
    float e = __expf(x) - 1.0f;
    return x > 0.0f ? x : e;
}

__device__ __forceinline__ unsigned long long pack2(float x) {
    unsigned long long r;
    unsigned int u = __float_as_uint(x);
    asm("mov.b64 %0, {%1, %1};" : "=l"(r) : "r"(u));
    return r;
}
__device__ __forceinline__ void unpack2(unsigned long long d, float& lo, float& hi) {
    unsigned int a, b;
    asm("mov.b64 {%0, %1}, %2;" : "=r"(a), "=r"(b) : "l"(d));
    lo = __uint_as_float(a);
    hi = __uint_as_float(b);
}
__device__ __forceinline__ unsigned long long fma2(unsigned long long a,
                                                   unsigned long long b,
                                                   unsigned long long c) {
    unsigned long long d;
    asm("fma.rn.f32x2 %0, %1, %2, %3;" : "=l"(d) : "l"(a), "l"(b), "l"(c));
    return d;
}

// 32-vec @ 32x32 smem matrix + bias, optional elu. Weights: row-major f32,
// viewed as u64 pairs (k even). All smem reads are warp-uniform broadcasts.
__device__ __forceinline__ void mv32(const float v[HH],
                                     const unsigned long long* __restrict__ sW,
                                     const unsigned long long* __restrict__ sBias,
                                     float out[HH], bool act) {
    unsigned long long acc[16];
    #pragma unroll
    for (int k2 = 0; k2 < 16; k2++) acc[k2] = sBias[k2];
    #pragma unroll
    for (int f = 0; f < 32; f++) {
        unsigned long long vv = pack2(v[f]);
        const ulonglong2* row = reinterpret_cast<const ulonglong2*>(sW + f * 16);
        #pragma unroll
        for (int q = 0; q < 8; q++) {
            ulonglong2 ww = row[q];
            acc[2*q]     = fma2(vv, ww.x, acc[2*q]);
            acc[2*q + 1] = fma2(vv, ww.y, acc[2*q + 1]);
        }
    }
    #pragma unroll
    for (int k2 = 0; k2 < 16; k2++) {
        float lo, hi;
        unpack2(acc[k2], lo, hi);
        out[2*k2]     = act ? eluf(lo) : lo;
        out[2*k2 + 1] = act ? eluf(hi) : hi;
    }
}

// ---------- Kernel A: node MLP + pa/pb projections ----------
__global__ void __launch_bounds__(128)
node_kernel(const float* __restrict__ x,
            const float* __restrict__ msk,
            const float* __restrict__ w0, const float* __restrict__ b0,
            const float* __restrict__ w1, const float* __restrict__ b1,
            const float* __restrict__ w2, const float* __restrict__ b2,
            const float* __restrict__ pw0) {
    __shared__ __align__(16) unsigned long long sW0[512], sW1[512];
    __shared__ __align__(16) unsigned long long sB0[16], sB1[16];
    __shared__ float sW2[FF*NODE_OUT];           // 256
    __shared__ float sWa[NODE_OUT*HH];           // 256
    __shared__ float sWb[NODE_OUT*HH];           // 256
    __shared__ float sB2[NODE_OUT];

    int tid = threadIdx.x;
    const unsigned long long* gw0 = reinterpret_cast<const unsigned long long*>(w0);
    const unsigned long long* gw1 = reinterpret_cast<const unsigned long long*>(w1);
    for (int idx = tid; idx < 512; idx += 128) { sW0[idx] = gw0[idx]; sW1[idx] = gw1[idx]; }
    for (int idx = tid; idx < 256; idx += 128) {
        sW2[idx] = w2[idx];
        sWa[idx] = pw0[idx];                       // rows 0..7
        sWb[idx] = pw0[NODE_OUT*HH + idx];         // rows 8..15
    }
    if (tid < 16) {
        sB0[tid] = reinterpret_cast<const unsigned long long*>(b0)[tid];
        sB1[tid] = reinterpret_cast<const unsigned long long*>(b1)[tid];
    }
    if (tid < NODE_OUT) sB2[tid] = b2[tid];
    __syncthreads();

    int r = blockIdx.x * 128 + tid;

    float xr[FF];
    const float4* gx4 = reinterpret_cast<const float4*>(x + (size_t)r * FF);
    #pragma unroll
    for (int q = 0; q < 8; q++) {
        float4 t = gx4[q];
        xr[4*q] = t.x; xr[4*q+1] = t.y; xr[4*q+2] = t.z; xr[4*q+3] = t.w;
    }

    float h0[HH], h1[HH];
    mv32(xr, sW0, sB0, h0, true);
    mv32(h0, sW1, sB1, h1, true);

    float m = msk[r];
    float np[NODE_OUT];
    #pragma unroll
    for (int k = 0; k < NODE_OUT; k++) {
        float a = sB2[k];
        #pragma unroll
        for (int f = 0; f < 32; f++) a = fmaf(h1[f], sW2[f*NODE_OUT + k], a);
        np[k] = eluf(a) * m;
    }

    float pa[HH], pb[HH];
    #pragma unroll
    for (int k = 0; k < 32; k++) { pa[k] = 0.f; pb[k] = 0.f; }
    #pragma unroll
    for (int c = 0; c < NODE_OUT; c++) {
        float nc = np[c];
        #pragma unroll
        for (int k = 0; k < 32; k++) {
            pa[k] = fmaf(nc, sWa[c*HH + k], pa[k]);
            pb[k] = fmaf(nc, sWb[c*HH + k], pb[k]);
        }
    }
    float4* gpa4 = reinterpret_cast<float4*>(g_pa_buf + (size_t)r * HH);
    float4* gpb4 = reinterpret_cast<float4*>(g_pb_buf + (size_t)r * HH);
    #pragma unroll
    for (int q = 0; q < 8; q++) {
        gpa4[q] = make_float4(pa[4*q], pa[4*q+1], pa[4*q+2], pa[4*q+3]);
        gpb4[q] = make_float4(pb[4*q], pb[4*q+1], pb[4*q+2], pb[4*q+3]);
    }
}

// ---------- Kernel B: pair stage ----------
// grid: (16 i-tiles, 64 bins), 128 threads; thread j = lane owns pair (i, j)
__global__ void __launch_bounds__(128)
pair_kernel(const float* __restrict__ pb0,
            const float* __restrict__ pw1, const float* __restrict__ pb1,
            const float* __restrict__ pw2, const float* __restrict__ pb2,
            float* __restrict__ out) {
    __shared__ __align__(16) float s_pb[PP * 36];           // padded stride 36 floats
    __shared__ __align__(16) float s_paib[TI * HH];
    __shared__ __align__(16) unsigned long long sW1[512], sW2[512];
    __shared__ __align__(16) unsigned long long sB1[16], sB2[16];

    int tid = threadIdx.x;
    int bin = blockIdx.y;
    int i0  = blockIdx.x * TI;

    // pb tile for this bin (128 x 32), padded rows
    const float4* gpb4 = reinterpret_cast<const float4*>(g_pb_buf + (size_t)bin * PP * HH);
    float4* dst = reinterpret_cast<float4*>(s_pb + tid * 36);
    #pragma unroll
    for (int q = 0; q < 8; q++) dst[q] = gpb4[tid * 8 + q];

    // pa rows for this i-tile, with pair_b0 pre-added
    for (int idx = tid; idx < TI * HH; idx += 128) {
        int ii = idx >> 5, f = idx & 31;
        s_paib[idx] = g_pa_buf[(size_t)(bin * PP + i0 + ii) * HH + f] + pb0[f];
    }

    const unsigned long long* gw1 = reinterpret_cast<const unsigned long long*>(pw1);
    const unsigned long long* gw2 = reinterpret_cast<const unsigned long long*>(pw2);
    for (int idx = tid; idx < 512; idx += 128) { sW1[idx] = gw1[idx]; sW2[idx] = gw2[idx]; }
    if (tid < 16) {
        sB1[tid] = reinterpret_cast<const unsigned long long*>(pb1)[tid];
        sB2[tid] = reinterpret_cast<const unsigned long long*>(pb2)[tid];
    }
    __syncthreads();

    int j = tid;
    const float4* pbrow = reinterpret_cast<const float4*>(s_pb + j * 36);
    float4* outp = reinterpret_cast<float4*>(out)
                 + ((size_t)(bin * PP + i0) * PP + j) * (OUTD / 4);

    #pragma unroll 1
    for (int ii = 0; ii < TI; ii++) {
        const float4* pib4 = reinterpret_cast<const float4*>(s_paib + ii * HH);
        float v[HH];
        #pragma unroll
        for (int q = 0; q < 8; q++) {
            float4 pv = pbrow[q];
            float4 pi = pib4[q];
            v[4*q]   = eluf(pi.x + pv.x);
            v[4*q+1] = eluf(pi.y + pv.y);
            v[4*q+2] = eluf(pi.z + pv.z);
            v[4*q+3] = eluf(pi.w + pv.w);
        }
        float w[HH], o[HH];
        mv32(v, sW1, sB1, w, true);
        mv32(w, sW2, sB2, o, true);

        #pragma unroll
        for (int q = 0; q < 8; q++)
            outp[q] = make_float4(o[4*q], o[4*q+1], o[4*q+2], o[4*q+3]);
        outp += (size_t)PP * (OUTD / 4);
    }
}

// ---------- launch ----------
extern "C" void kernel_launch(void* const* d_in, const int* in_sizes, int n_in,
                              void* d_out, int out_size) {
    const float* x    = (const float*)d_in[0];
    const float* msk  = (const float*)d_in[1];
    const float* nw0  = (const float*)d_in[2];
    const float* nb0  = (const float*)d_in[3];
    const float* nw1  = (const float*)d_in[4];
    const float* nb1  = (const float*)d_in[5];
    const float* nw2  = (const float*)d_in[6];
    const float* nb2  = (const float*)d_in[7];
    const float* pw0  = (const float*)d_in[8];
    const float* pb0  = (const float*)d_in[9];
    const float* pw1  = (const float*)d_in[10];
    const float* pb1  = (const float*)d_in[11];
    const float* pw2  = (const float*)d_in[12];
    const float* pb2  = (const float*)d_in[13];
    float* out = (float*)d_out;

    node_kernel<<<ROWS / 128, 128>>>(x, msk, nw0, nb0, nw1, nb1, nw2, nb2, pw0);
    pair_kernel<<<dim3(PP / TI, BINS), 128>>>(pb0, pw1, pb1, pw2, pb2, out);
}